// round 3
// baseline (speedup 1.0000x reference)
#include <cuda_runtime.h>
#include <math.h>

#define AMAX   76725
#define NCLS   80
#define KTOP   1000
#define NBINS  8192
#define NCAND  2048      // power of 2 for bitonic sort; >= candidates collected
#define NWORDS 16        // ceil(KTOP/64)
#define NTHR   1024

// Shared memory layout (byte offsets into dynamic smem)
#define OFF_CAND   0                       // u64[2048]            16384 B
#define OFF_MASK   16384                   // u64[16000]          128000 B (aliases hist u32[8192])
#define OFF_SCORE  144384                  // float[1000]           4000 B
#define OFF_BOX    148384                  // float4[1000]         16000 B
#define OFF_AREA   164384                  // float[1000]           4000 B
#define SMEM_BYTES 168448

__device__ float4 g_boxes[AMAX];

// ---------------------------------------------------------------------------
// Kernel 1: decode + clip all anchor boxes (class independent)
// ---------------------------------------------------------------------------
__global__ void decode_kernel(const float* __restrict__ reg,
                              const float* __restrict__ anch,
                              int A, float W, float H) {
    int a = blockIdx.x * blockDim.x + threadIdx.x;
    if (a >= A) return;
    float4 an = reinterpret_cast<const float4*>(anch)[a];
    float4 dl = reinterpret_cast<const float4*>(reg)[a];
    float aw = an.z - an.x;
    float ah = an.w - an.y;
    float cx = an.x + 0.5f * aw;
    float cy = an.y + 0.5f * ah;
    float pcx = cx + dl.x * 0.1f * aw;
    float pcy = cy + dl.y * 0.1f * ah;
    float pw = expf(dl.z * 0.2f) * aw;
    float ph = expf(dl.w * 0.2f) * ah;
    float4 b;
    b.x = fmaxf(pcx - 0.5f * pw, 0.0f);
    b.y = fmaxf(pcy - 0.5f * ph, 0.0f);
    b.z = fminf(pcx + 0.5f * pw, W);
    b.w = fminf(pcy + 0.5f * ph, H);
    g_boxes[a] = b;
}

// Orderable key for float (handles negatives; positives get MSB set)
__device__ __forceinline__ unsigned fkey(float s) {
    unsigned b = __float_as_uint(s);
    return (b & 0x80000000u) ? ~b : (b | 0x80000000u);
}
__device__ __forceinline__ float fkey_inv(unsigned k) {
    return __uint_as_float((k & 0x80000000u) ? (k & 0x7FFFFFFFu) : ~k);
}

// ---------------------------------------------------------------------------
// Kernel 2: per-class top-k + NMS + output. One block per class.
// ---------------------------------------------------------------------------
__global__ __launch_bounds__(NTHR, 1)
void topk_nms_kernel(const float* __restrict__ cls,
                     float* __restrict__ out,
                     int A, int C) {
    extern __shared__ char sbase[];
    unsigned long long* cand = (unsigned long long*)(sbase + OFF_CAND);
    unsigned long long* mask = (unsigned long long*)(sbase + OFF_MASK);
    unsigned int*       hist = (unsigned int*)(sbase + OFF_MASK);   // alias
    float*            sscore = (float*)(sbase + OFF_SCORE);
    float4*             sbox = (float4*)(sbase + OFF_BOX);
    float*             sarea = (float*)(sbase + OFF_AREA);

    __shared__ int sT;
    __shared__ int sCnt;
    __shared__ unsigned long long salive[NWORDS];
    __shared__ unsigned long long skeep[NWORDS];

    const int tid = threadIdx.x;
    const int c   = blockIdx.x;

    // ---- Phase 1: histogram of scores (linear bins over [0,1)) ----
    for (int i = tid; i < NBINS; i += NTHR) hist[i] = 0u;
    if (tid == 0) sCnt = 0;
    __syncthreads();

    for (int a = tid; a < A; a += NTHR) {
        float s = cls[a * C + c];
        int b = (int)(s * (float)NBINS);
        b = max(0, min(NBINS - 1, b));
        atomicAdd(&hist[b], 1u);
    }
    __syncthreads();

    // ---- Phase 2: find threshold bin (suffix sum until >= KTOP) ----
    if (tid == 0) {
        int cum = 0, t;
        for (t = NBINS - 1; t >= 0; t--) {
            cum += (int)hist[t];
            if (cum >= KTOP) break;
        }
        sT = (t < 0) ? 0 : t;
    }
    __syncthreads();

    // ---- Phase 3: collect candidates (superset of top-K) ----
    {
        int T = sT;
        for (int a = tid; a < A; a += NTHR) {
            float s = cls[a * C + c];
            int b = (int)(s * (float)NBINS);
            b = max(0, min(NBINS - 1, b));
            if (b >= T) {
                int p = atomicAdd(&sCnt, 1);
                if (p < NCAND) {
                    unsigned long long key =
                        ((unsigned long long)fkey(s) << 32) |
                        (unsigned long long)(0xFFFFFFFFu - (unsigned)a);
                    cand[p] = key;
                }
            }
        }
    }
    __syncthreads();
    int n = min(sCnt, NCAND);
    for (int i = tid; i < NCAND; i += NTHR)
        if (i >= n) cand[i] = 0ull;   // sentinel: sorts last
    __syncthreads();

    // ---- Phase 4: bitonic sort descending (score desc, index asc on ties) ----
    for (int k = 2; k <= NCAND; k <<= 1) {
        for (int j = k >> 1; j > 0; j >>= 1) {
            for (int i = tid; i < NCAND; i += NTHR) {
                int ixj = i ^ j;
                if (ixj > i) {
                    unsigned long long a0 = cand[i], b0 = cand[ixj];
                    bool desc = ((i & k) == 0);
                    bool swap = desc ? (a0 < b0) : (a0 > b0);
                    if (swap) { cand[i] = b0; cand[ixj] = a0; }
                }
            }
            __syncthreads();
        }
    }

    // ---- Phase 5: extract top-K, gather boxes, build validity bitmap ----
    for (int i = tid; i < KTOP; i += NTHR) {
        unsigned long long v = cand[i];
        float s = fkey_inv((unsigned)(v >> 32));
        unsigned a = 0xFFFFFFFFu - (unsigned)(v & 0xFFFFFFFFull);
        float4 bb = (a < (unsigned)A) ? g_boxes[a] : make_float4(0.f, 0.f, 0.f, 0.f);
        if (!(a < (unsigned)A)) s = 0.f;
        sbox[i]   = bb;
        sarea[i]  = (bb.z - bb.x) * (bb.w - bb.y);
        sscore[i] = s;
    }
    if (tid < NWORDS) salive[tid] = 0ull;
    __syncthreads();
    for (int i = tid; i < KTOP; i += NTHR)
        if (sscore[i] > 0.001f)
            atomicOr(&salive[i >> 6], 1ull << (i & 63));

    // zero mask (hist alias no longer needed)
    for (int i = tid; i < KTOP * NWORDS; i += NTHR) mask[i] = 0ull;
    __syncthreads();

    // ---- Phase 6: pairwise IoU suppression bitmask (upper triangle only) ----
    {
        const int warp = tid >> 5;
        const int lane = tid & 31;
        const int wb = warp & 15;   // word column (j block of 64)
        const int rh = warp >> 4;   // row interleave 0/1
        const int j1 = wb * 64 + lane;
        const int j2 = j1 + 32;
        float4 B1 = (j1 < KTOP) ? sbox[j1] : make_float4(0.f, 0.f, 0.f, 0.f);
        float4 B2 = (j2 < KTOP) ? sbox[j2] : make_float4(0.f, 0.f, 0.f, 0.f);
        float ar1 = (j1 < KTOP) ? sarea[j1] : 0.f;
        float ar2 = (j2 < KTOP) ? sarea[j2] : 0.f;

        const int iEnd = min(KTOP, wb * 64 + 63);  // rows with any j>i in this word
        for (int i = rh; i < iEnd; i += 2) {
            float4 BI = sbox[i];
            float  ai = sarea[i];

            float xx1 = fmaxf(BI.x, B1.x), yy1 = fmaxf(BI.y, B1.y);
            float xx2 = fminf(BI.z, B1.z), yy2 = fminf(BI.w, B1.w);
            float iw = fmaxf(xx2 - xx1, 0.f), ih = fmaxf(yy2 - yy1, 0.f);
            float inter = iw * ih;
            bool p1 = (j1 > i) && (j1 < KTOP) &&
                      (inter > 0.5f * (ai + ar1 - inter + 1e-8f));

            xx1 = fmaxf(BI.x, B2.x); yy1 = fmaxf(BI.y, B2.y);
            xx2 = fminf(BI.z, B2.z); yy2 = fminf(BI.w, B2.w);
            iw = fmaxf(xx2 - xx1, 0.f); ih = fmaxf(yy2 - yy1, 0.f);
            inter = iw * ih;
            bool p2 = (j2 > i) && (j2 < KTOP) &&
                      (inter > 0.5f * (ai + ar2 - inter + 1e-8f));

            unsigned m1 = __ballot_sync(0xFFFFFFFFu, p1);
            unsigned m2 = __ballot_sync(0xFFFFFFFFu, p2);
            if (lane == 0)
                mask[i * NWORDS + wb] = ((unsigned long long)m2 << 32) | m1;
        }
    }
    __syncthreads();

    // ---- Phase 7: serial greedy NMS scan (warp 0; speculative row loads) ----
    if (tid < 32) {
        const int lane = tid;
        unsigned long long rem = 0ull;
        unsigned long long alv = (lane < NWORDS) ? salive[lane] : 0ull;
        for (int i = 0; i < KTOP; i++) {
            // speculative load: off the critical path
            unsigned long long row = (lane < NWORDS) ? mask[i * NWORDS + lane] : 0ull;
            unsigned long long cur = alv & ~rem;
            unsigned long long curw = __shfl_sync(0xFFFFFFFFu, cur, i >> 6);
            if ((curw >> (i & 63)) & 1ull) rem |= row;
        }
        if (lane < NWORDS) skeep[lane] = alv & ~rem;
    }
    __syncthreads();

    // ---- Phase 8: write padded outputs: scores, labels, boxes, keep ----
    float* out_scores = out;
    float* out_labels = out + (size_t)NCLS * KTOP;
    float* out_boxes  = out + (size_t)2 * NCLS * KTOP;
    float* out_keep   = out + (size_t)6 * NCLS * KTOP;
    for (int i = tid; i < KTOP; i += NTHR) {
        bool kp = (skeep[i >> 6] >> (i & 63)) & 1ull;
        float kf = kp ? 1.0f : 0.0f;
        int o = c * KTOP + i;
        out_scores[o] = sscore[i] * kf;
        out_labels[o] = (float)c;
        float4 bb = sbox[i];
        reinterpret_cast<float4*>(out_boxes)[o] =
            make_float4(bb.x * kf, bb.y * kf, bb.z * kf, bb.w * kf);
        out_keep[o] = kf;
    }
}

// ---------------------------------------------------------------------------
extern "C" void kernel_launch(void* const* d_in, const int* in_sizes, int n_in,
                              void* d_out, int out_size) {
    const float* cls  = (const float*)d_in[1];
    const float* reg  = (const float*)d_in[2];
    const float* anch = (const float*)d_in[3];

    int A = in_sizes[2] / 4;                 // 76725
    int C = in_sizes[1] / A;                 // 80
    int HW = in_sizes[0] / 3;                // 640*640
    float H = floorf(sqrtf((float)HW) + 0.5f);  // 640 (square image)

    decode_kernel<<<(A + 255) / 256, 256>>>(reg, anch, A, H, H);

    cudaFuncSetAttribute(topk_nms_kernel,
                         cudaFuncAttributeMaxDynamicSharedMemorySize,
                         SMEM_BYTES);
    topk_nms_kernel<<<C, NTHR, SMEM_BYTES>>>(cls, (float*)d_out, A, C);
}

// round 4
// speedup vs baseline: 1.3006x; 1.3006x over previous
#include <cuda_runtime.h>
#include <math.h>

#define AMAX   76725
#define NCLS   80
#define KTOP   1000
#define NCAND  2048
#define NWORDS 16
#define NBINS  8192
#define THR_SEL 0.98f

__device__ float4              g_boxes[AMAX];
__device__ unsigned long long  g_cand[NCLS * NCAND];
__device__ int                 g_cnt[NCLS];
__device__ float               g_scoreK[NCLS * KTOP];
__device__ float4              g_boxK[NCLS * KTOP];
__device__ float               g_areaK[NCLS * KTOP];
__device__ unsigned long long  g_alive[NCLS * NWORDS];
__device__ unsigned long long  g_mask[NCLS * KTOP * NWORDS];  // zero-init; only words wb>=i>>6 ever written

// ---------------------------------------------------------------------------
__device__ __forceinline__ unsigned fkey(float s) {
    unsigned b = __float_as_uint(s);
    return (b & 0x80000000u) ? ~b : (b | 0x80000000u);
}
__device__ __forceinline__ float fkey_inv(unsigned k) {
    return __uint_as_float((k & 0x80000000u) ? (k & 0x7FFFFFFFu) : ~k);
}
__device__ __forceinline__ unsigned long long mkkey(float s, unsigned a) {
    return ((unsigned long long)fkey(s) << 32) |
           (unsigned long long)(0xFFFFFFFFu - a);
}

// ---------------------------------------------------------------------------
__global__ void init_kernel() {
    int t = blockIdx.x * blockDim.x + threadIdx.x;
    if (t < NCLS) g_cnt[t] = 0;
}

// ---------------------------------------------------------------------------
__global__ void decode_kernel(const float* __restrict__ reg,
                              const float* __restrict__ anch,
                              int A, float W, float H) {
    int a = blockIdx.x * blockDim.x + threadIdx.x;
    if (a >= A) return;
    float4 an = reinterpret_cast<const float4*>(anch)[a];
    float4 dl = reinterpret_cast<const float4*>(reg)[a];
    float aw = an.z - an.x;
    float ah = an.w - an.y;
    float cx = an.x + 0.5f * aw;
    float cy = an.y + 0.5f * ah;
    float pcx = cx + dl.x * 0.1f * aw;
    float pcy = cy + dl.y * 0.1f * ah;
    float pw = expf(dl.z * 0.2f) * aw;
    float ph = expf(dl.w * 0.2f) * ah;
    float4 b;
    b.x = fmaxf(pcx - 0.5f * pw, 0.0f);
    b.y = fmaxf(pcy - 0.5f * ph, 0.0f);
    b.z = fminf(pcx + 0.5f * pw, W);
    b.w = fminf(pcy + 0.5f * ph, H);
    g_boxes[a] = b;
}

// ---------------------------------------------------------------------------
// Coalesced single-pass candidate selection with fixed threshold.
// Requires C%4==0 and 4*gridthreads%C==0 (host guarantees, else skipped).
__global__ __launch_bounds__(320)
void select_kernel(const float* __restrict__ cls, int A, int C, int astep) {
    int gthreads = gridDim.x * blockDim.x;
    int t = blockIdx.x * blockDim.x + threadIdx.x;
    int nf4 = (A * C) >> 2;
    const float4* cls4 = reinterpret_cast<const float4*>(cls);
    int e0 = t << 2;
    int a  = e0 / C;
    int c0 = e0 - a * C;     // constant per thread across iterations
    for (int f = t; f < nf4; f += gthreads, a += astep) {
        float4 v = cls4[f];
        if (v.x > THR_SEL) {
            int p = atomicAdd(&g_cnt[c0 + 0], 1);
            if (p < NCAND) g_cand[(c0 + 0) * NCAND + p] = mkkey(v.x, (unsigned)a);
        }
        if (v.y > THR_SEL) {
            int p = atomicAdd(&g_cnt[c0 + 1], 1);
            if (p < NCAND) g_cand[(c0 + 1) * NCAND + p] = mkkey(v.y, (unsigned)a);
        }
        if (v.z > THR_SEL) {
            int p = atomicAdd(&g_cnt[c0 + 2], 1);
            if (p < NCAND) g_cand[(c0 + 2) * NCAND + p] = mkkey(v.z, (unsigned)a);
        }
        if (v.w > THR_SEL) {
            int p = atomicAdd(&g_cnt[c0 + 3], 1);
            if (p < NCAND) g_cand[(c0 + 3) * NCAND + p] = mkkey(v.w, (unsigned)a);
        }
    }
}

// ---------------------------------------------------------------------------
// Guard: exact histogram-based reselection if the fixed threshold failed.
__global__ __launch_bounds__(1024)
void fixup_kernel(const float* __restrict__ cls, int A, int C) {
    int c = blockIdx.x, tid = threadIdx.x;
    int cnt0 = g_cnt[c];
    if (cnt0 >= KTOP && cnt0 <= NCAND) return;   // uniform early exit

    __shared__ unsigned hist[NBINS];
    __shared__ int sT, sCnt;
    for (int i = tid; i < NBINS; i += 1024) hist[i] = 0u;
    if (tid == 0) sCnt = 0;
    __syncthreads();

    for (int a = tid; a < A; a += 1024) {
        float s = cls[a * C + c];
        int b = (int)(s * (float)NBINS);
        b = max(0, min(NBINS - 1, b));
        atomicAdd(&hist[b], 1u);
    }
    __syncthreads();

    if (tid == 0) {
        int cum = 0, t;
        for (t = NBINS - 1; t >= 0; t--) {
            cum += (int)hist[t];
            if (cum >= KTOP) break;
        }
        sT = (t < 0) ? 0 : t;
    }
    __syncthreads();

    int T = sT;
    for (int a = tid; a < A; a += 1024) {
        float s = cls[a * C + c];
        int b = (int)(s * (float)NBINS);
        b = max(0, min(NBINS - 1, b));
        if (b >= T) {
            int p = atomicAdd(&sCnt, 1);
            if (p < NCAND) g_cand[c * NCAND + p] = mkkey(s, (unsigned)a);
        }
    }
    __syncthreads();
    if (tid == 0) g_cnt[c] = min(sCnt, NCAND);
}

// ---------------------------------------------------------------------------
// Per-class exact sort of candidates, extract top-K with boxes/areas/alive.
__global__ __launch_bounds__(1024)
void sort_kernel(int A) {
    __shared__ unsigned long long cand[NCAND];
    __shared__ unsigned long long salive[NWORDS];
    int c = blockIdx.x, tid = threadIdx.x;
    int n = min(g_cnt[c], NCAND);

    for (int i = tid; i < NCAND; i += 1024)
        cand[i] = (i < n) ? g_cand[c * NCAND + i] : 0ull;
    if (tid < NWORDS) salive[tid] = 0ull;
    __syncthreads();

    for (int k = 2; k <= NCAND; k <<= 1) {
        for (int j = k >> 1; j > 0; j >>= 1) {
            for (int i = tid; i < NCAND; i += 1024) {
                int ixj = i ^ j;
                if (ixj > i) {
                    unsigned long long a0 = cand[i], b0 = cand[ixj];
                    bool desc = ((i & k) == 0);
                    bool swap = desc ? (a0 < b0) : (a0 > b0);
                    if (swap) { cand[i] = b0; cand[ixj] = a0; }
                }
            }
            __syncthreads();
        }
    }

    if (tid < KTOP) {
        unsigned long long v = cand[tid];
        float s = fkey_inv((unsigned)(v >> 32));
        unsigned a = 0xFFFFFFFFu - (unsigned)(v & 0xFFFFFFFFull);
        bool valid = (a < (unsigned)A);
        float4 bb = valid ? g_boxes[a] : make_float4(0.f, 0.f, 0.f, 0.f);
        if (!valid) s = 0.f;
        int o = c * KTOP + tid;
        g_scoreK[o] = s;
        g_boxK[o]   = bb;
        g_areaK[o]  = (bb.z - bb.x) * (bb.w - bb.y);
        if (s > 0.001f) atomicOr(&salive[tid >> 6], 1ull << (tid & 63));
    }
    __syncthreads();
    if (tid < NWORDS) g_alive[c * NWORDS + tid] = salive[tid];
}

// ---------------------------------------------------------------------------
// IoU suppression bitmask; grid (C, 8) for chip-wide balance.
__global__ __launch_bounds__(512)
void mask_kernel() {
    __shared__ float4 sbox[1024];
    __shared__ float  sarea[1024];
    int c = blockIdx.x, ph = blockIdx.y, tid = threadIdx.x;

    for (int i = tid; i < 1024; i += 512) {
        if (i < KTOP) {
            sbox[i]  = g_boxK[c * KTOP + i];
            sarea[i] = g_areaK[c * KTOP + i];
        } else {
            sbox[i]  = make_float4(3e8f, 3e8f, 3e8f, 3e8f);  // inter=0 with anything
            sarea[i] = 0.f;
        }
    }
    __syncthreads();

    int warp = tid >> 5, lane = tid & 31;
    int wb = warp;                    // word column 0..15
    int j1 = wb * 64 + lane;
    int j2 = j1 + 32;
    float4 B1 = sbox[j1], B2 = sbox[j2];
    float ar1 = sarea[j1], ar2 = sarea[j2];

    int iLim = wb * 64 + 64;          // includes the all-zero diagonal-end row
    if (iLim > KTOP) iLim = KTOP;
    unsigned long long* mrow = g_mask + (size_t)c * KTOP * NWORDS + wb;

    for (int i = ph; i < iLim; i += 8) {
        float4 BI = sbox[i];
        float  ai = sarea[i];

        float xx1 = fmaxf(BI.x, B1.x), yy1 = fmaxf(BI.y, B1.y);
        float xx2 = fminf(BI.z, B1.z), yy2 = fminf(BI.w, B1.w);
        float inter = fmaxf(xx2 - xx1, 0.f) * fmaxf(yy2 - yy1, 0.f);
        bool p1 = (j1 > i) && (inter > 0.5f * (ai + ar1 - inter + 1e-8f));

        xx1 = fmaxf(BI.x, B2.x); yy1 = fmaxf(BI.y, B2.y);
        xx2 = fminf(BI.z, B2.z); yy2 = fminf(BI.w, B2.w);
        inter = fmaxf(xx2 - xx1, 0.f) * fmaxf(yy2 - yy1, 0.f);
        bool p2 = (j2 > i) && (inter > 0.5f * (ai + ar2 - inter + 1e-8f));

        unsigned m1 = __ballot_sync(0xFFFFFFFFu, p1);
        unsigned m2 = __ballot_sync(0xFFFFFFFFu, p2);
        if (lane == 0)
            mrow[(size_t)i * NWORDS] = ((unsigned long long)m2 << 32) | m1;
    }
}

// ---------------------------------------------------------------------------
// Serial greedy scan (register-resident, 12-cyc/bit chain) + output write.
#define SCAN_SMEM (KTOP * NWORDS * 8)
__global__ __launch_bounds__(256)
void scan_kernel(float* __restrict__ out, int C) {
    extern __shared__ unsigned long long smask[];
    __shared__ unsigned long long skeep[NWORDS];
    int c = blockIdx.x, tid = threadIdx.x;

    const uint4* src = reinterpret_cast<const uint4*>(g_mask + (size_t)c * KTOP * NWORDS);
    uint4* dst = reinterpret_cast<uint4*>(smask);
    for (int i = tid; i < KTOP * NWORDS / 2; i += 256) dst[i] = src[i];
    __syncthreads();

    if (tid == 0) {
        unsigned long long cur[NWORDS];
#pragma unroll
        for (int w = 0; w < NWORDS; w++) cur[w] = g_alive[c * NWORDS + w];

#pragma unroll
        for (int w = 0; w < NWORDS; w++) {
            int bmax = KTOP - w * 64;
            if (bmax > 64) bmax = 64;
            for (int b = 0; b < bmax; b++) {
                const ulonglong2* row2 =
                    reinterpret_cast<const ulonglong2*>(smask + (w * 64 + b) * NWORDS);
                // all-ones iff candidate i=w*64+b still alive (kept)
                unsigned long long m =
                    (unsigned long long)(((long long)(cur[w] << (63 - b))) >> 63);
#pragma unroll
                for (int p = (w >> 1); p < 8; p++) {
                    ulonglong2 r = row2[p];   // words < w are zero in g_mask: harmless
                    cur[2 * p]     &= ~(r.x & m);
                    cur[2 * p + 1] &= ~(r.y & m);
                }
            }
        }
#pragma unroll
        for (int w = 0; w < NWORDS; w++) skeep[w] = cur[w];
    }
    __syncthreads();

    float* out_scores = out;
    float* out_labels = out + (size_t)C * KTOP;
    float* out_boxes  = out + (size_t)2 * C * KTOP;
    float* out_keep   = out + (size_t)6 * C * KTOP;
    for (int i = tid; i < KTOP; i += 256) {
        bool kp = (skeep[i >> 6] >> (i & 63)) & 1ull;
        float kf = kp ? 1.0f : 0.0f;
        int o = c * KTOP + i;
        out_scores[o] = g_scoreK[o] * kf;
        out_labels[o] = (float)c;
        float4 bb = g_boxK[o];
        reinterpret_cast<float4*>(out_boxes)[o] =
            make_float4(bb.x * kf, bb.y * kf, bb.z * kf, bb.w * kf);
        out_keep[o] = kf;
    }
}

// ---------------------------------------------------------------------------
extern "C" void kernel_launch(void* const* d_in, const int* in_sizes, int n_in,
                              void* d_out, int out_size) {
    const float* cls  = (const float*)d_in[1];
    const float* reg  = (const float*)d_in[2];
    const float* anch = (const float*)d_in[3];

    int A = in_sizes[2] / 4;                    // 76725
    int C = in_sizes[1] / A;                    // 80
    int HW = in_sizes[0] / 3;                   // 640*640
    float H = floorf(sqrtf((float)HW) + 0.5f);  // 640

    init_kernel<<<1, 128>>>();
    decode_kernel<<<(A + 255) / 256, 256>>>(reg, anch, A, H, H);

    const int SEL_BLOCKS = 1184, SEL_THREADS = 320;
    long long gthreads = (long long)SEL_BLOCKS * SEL_THREADS;
    bool fast_ok = (C > 0) && ((C & 3) == 0) && (((A * (long long)C) & 3) == 0) &&
                   (((4 * gthreads) % C) == 0);
    if (fast_ok) {
        int astep = (int)((4 * gthreads) / C);
        select_kernel<<<SEL_BLOCKS, SEL_THREADS>>>(cls, A, C, astep);
    }
    // Guard: exact reselection for any class whose count is out of [KTOP, NCAND]
    fixup_kernel<<<C, 1024>>>(cls, A, C);

    sort_kernel<<<C, 1024>>>(A);
    mask_kernel<<<dim3(C, 8), 512>>>();

    cudaFuncSetAttribute(scan_kernel,
                         cudaFuncAttributeMaxDynamicSharedMemorySize, SCAN_SMEM);
    scan_kernel<<<C, 256, SCAN_SMEM>>>((float*)d_out, C);
}